// round 3
// baseline (speedup 1.0000x reference)
#include <cuda_runtime.h>
#include <cuda_bf16.h>
#include <math.h>

#define BB 256
#define LL 128
#define IN_DIM 6
#define DD 256
#define HH 8
#define NLAYER 6
#define NE 8
#define NTOPK 2
#define FFD 1024
#define NHEADS 5
#define NMOE_L 3
#define DKH 32
#define TT (BB*LL)            // 32768 tokens
#define NENT (TT*NTOPK)       // 65536 routed entries
#define TILE_M 128
#define MAX_TILES (NENT/TILE_M + NE)   // 520

// ---------------- scratch (static device globals; no allocation) ----------------
__device__ float g_h[TT*DD];
__device__ float g_q[TT*DD];
__device__ float g_k[TT*DD];
__device__ float g_v[TT*DD];
__device__ float g_attn[TT*DD];
__device__ float g_ff[(size_t)NENT*FFD];   // 256 MB expert-hidden
__device__ float g_out2[(size_t)NENT*DD];  // 67 MB expert outputs (pre-combine)
__device__ int   g_entry_token[NENT];
__device__ int   g_tok_i0[TT], g_tok_i1[TT];
__device__ int   g_tok_slot0[TT], g_tok_slot1[TT];
__device__ float g_tok_w0[TT], g_tok_w1[TT];
__device__ int   g_counts[NE], g_offs[NE+1], g_cursor[NE];
__device__ int   g_tile_e[MAX_TILES], g_tile_start[MAX_TILES], g_tile_end[MAX_TILES];
__device__ int   g_ntiles;

// ---------------- embedding ----------------
__global__ void embed_kernel(const float* __restrict__ x,
                             const float* __restrict__ ew,
                             const float* __restrict__ eb) {
    int idx = blockIdx.x * 256 + threadIdx.x;
    if (idx >= TT*DD) return;
    int t = idx / DD, d = idx % DD;
    const float* xr = x + t * IN_DIM;
    float s = eb[d];
#pragma unroll
    for (int c = 0; c < IN_DIM; c++) s += xr[c] * ew[c*DD + d];
    g_h[idx] = s;
}

// ---------------- generic 128x128x16 SGEMM, 8x8 per thread ----------------
// Double-buffered smem + register prefetch: one __syncthreads per k-iteration,
// global loads for tile i+1 overlap the FFMA block of tile i.
// MODE 0: C = A@B (+Res)          (M,N,K given; grid = (M/128, N/128))
// MODE 1: MoE up: A rows gathered via entry_token, out = gelu(acc + b1[e]) -> C[slot*N+n]
// MODE 2: MoE down: A rows = contiguous slots, out = acc + b2[e][n] -> C[slot*N+n]
template<int MODE>
__global__ void gemm128(const float* __restrict__ A, const float* __restrict__ Bmat,
                        const float* __restrict__ bias, const float* __restrict__ Res,
                        float* __restrict__ C, int M, int N, int K)
{
    __shared__ float As[2][16][128];
    __shared__ float Bs[2][16][128];
    int tile = blockIdx.x;
    int n0 = blockIdx.y * 128;
    int m0 = 0, row_start = 0, row_end = 0;
    const float* Bp = Bmat;
    const float* biasp = bias;
    if (MODE == 0) {
        m0 = tile * 128;
    } else {
        if (tile >= g_ntiles) return;
        int e = g_tile_e[tile];
        row_start = g_tile_start[tile];
        row_end   = g_tile_end[tile];
        Bp    = Bmat + (size_t)e * K * N;
        biasp = bias + (size_t)e * N;
    }
    int tid = threadIdx.x;
    int ty = tid >> 4, tx = tid & 15;
    int ra0 = tid >> 2;            // 0..63
    int ca  = (tid & 3) << 2;      // 0,4,8,12
    const float* arow[2];
#pragma unroll
    for (int i = 0; i < 2; i++) {
        int r = ra0 + i*64;
        if (MODE == 0) {
            arow[i] = A + (size_t)(m0 + r) * K;
        } else if (MODE == 1) {
            int slot = row_start + r;
            int token = (slot < row_end) ? g_entry_token[slot] : 0;
            if (token < 0 || token >= TT) token = 0;
            arow[i] = A + (size_t)token * K;
        } else {
            int slot = row_start + r;
            if (slot >= NENT) slot = NENT - 1;
            arow[i] = A + (size_t)slot * K;
        }
    }
    int rb0 = tid >> 5;            // 0..7
    int cb  = (tid & 31) << 2;     // 0..124

    float4 a_reg[2], b_reg[2];
    // prologue: load k-tile 0 into registers, store to smem stage 0
#pragma unroll
    for (int i = 0; i < 2; i++)
        a_reg[i] = *reinterpret_cast<const float4*>(arow[i] + ca);
#pragma unroll
    for (int i = 0; i < 2; i++)
        b_reg[i] = *reinterpret_cast<const float4*>(Bp + (size_t)(rb0 + i*8) * N + n0 + cb);
#pragma unroll
    for (int i = 0; i < 2; i++) {
        As[0][ca+0][ra0 + i*64] = a_reg[i].x;
        As[0][ca+1][ra0 + i*64] = a_reg[i].y;
        As[0][ca+2][ra0 + i*64] = a_reg[i].z;
        As[0][ca+3][ra0 + i*64] = a_reg[i].w;
        *reinterpret_cast<float4*>(&Bs[0][rb0 + i*8][cb]) = b_reg[i];
    }
    __syncthreads();

    float acc[8][8] = {};
    int buf = 0;
    for (int k0 = 0; k0 < K; k0 += 16) {
        bool has_next = (k0 + 16 < K);
        // prefetch next tile into registers (overlaps FFMA block)
        if (has_next) {
#pragma unroll
            for (int i = 0; i < 2; i++)
                a_reg[i] = *reinterpret_cast<const float4*>(arow[i] + k0 + 16 + ca);
#pragma unroll
            for (int i = 0; i < 2; i++)
                b_reg[i] = *reinterpret_cast<const float4*>(Bp + (size_t)(k0 + 16 + rb0 + i*8) * N + n0 + cb);
        }
#pragma unroll
        for (int kk = 0; kk < 16; kk++) {
            float ra[8], rb[8];
#pragma unroll
            for (int i = 0; i < 8; i++) ra[i] = As[buf][kk][ty*8 + i];
#pragma unroll
            for (int j = 0; j < 8; j++) rb[j] = Bs[buf][kk][tx*8 + j];
#pragma unroll
            for (int i = 0; i < 8; i++)
#pragma unroll
                for (int j = 0; j < 8; j++)
                    acc[i][j] += ra[i] * rb[j];
        }
        if (has_next) {
            int nb = buf ^ 1;
#pragma unroll
            for (int i = 0; i < 2; i++) {
                As[nb][ca+0][ra0 + i*64] = a_reg[i].x;
                As[nb][ca+1][ra0 + i*64] = a_reg[i].y;
                As[nb][ca+2][ra0 + i*64] = a_reg[i].z;
                As[nb][ca+3][ra0 + i*64] = a_reg[i].w;
                *reinterpret_cast<float4*>(&Bs[nb][rb0 + i*8][cb]) = b_reg[i];
            }
            __syncthreads();
            buf = nb;
        }
    }
    if (MODE == 0) {
#pragma unroll
        for (int i = 0; i < 8; i++) {
            int m = m0 + ty*8 + i;
#pragma unroll
            for (int j = 0; j < 8; j++) {
                int n = n0 + tx*8 + j;
                float v = acc[i][j];
                if (Res) v += Res[(size_t)m*N + n];
                C[(size_t)m*N + n] = v;
            }
        }
    } else if (MODE == 1) {
#pragma unroll
        for (int i = 0; i < 8; i++) {
            int slot = row_start + ty*8 + i;
            if (slot >= row_end) continue;
#pragma unroll
            for (int j = 0; j < 8; j++) {
                int n = n0 + tx*8 + j;
                float xv = acc[i][j] + biasp[n];
                float gl = 0.5f * xv * (1.0f + erff(xv * 0.7071067811865475f));
                C[(size_t)slot*N + n] = gl;
            }
        }
    } else {
#pragma unroll
        for (int i = 0; i < 8; i++) {
            int slot = row_start + ty*8 + i;
            if (slot >= row_end) continue;
#pragma unroll
            for (int j = 0; j < 8; j++) {
                int n = n0 + tx*8 + j;
                C[(size_t)slot*N + n] = acc[i][j] + biasp[n];
            }
        }
    }
}

// ---------------- fused wave attention: one block per (b,h) ----------------
__global__ void attn_kernel(const float* __restrict__ wfreq,
                            const float* __restrict__ wphase, int layer)
{
    __shared__ float Ks[LL][DKH];
    __shared__ float Vs[LL][DKH];
    __shared__ float wave[LL];
    int bh = blockIdx.x;
    int b = bh / HH, h = bh % HH;
    int tid = threadIdx.x;                // 128 threads: 1 query row each
    float fr = wfreq[layer*HH + h];
    float ph = wphase[layer*HH + h];
    size_t base = ((size_t)b * LL) * DD + h * DKH;
    for (int idx = tid; idx < LL*DKH; idx += 128) {
        int r = idx >> 5, c = idx & 31;
        Ks[r][c] = g_k[base + (size_t)r*DD + c];
        Vs[r][c] = g_v[base + (size_t)r*DD + c];
    }
    if (tid < LL) wave[tid] = cosf(6.283185307179586f * fr * (float)tid + ph);
    __syncthreads();

    float q[DKH];
    size_t qb = base + (size_t)tid * DD;
#pragma unroll
    for (int c = 0; c < DKH; c++) q[c] = g_q[qb + c];

    float m = -1e30f, lsum = 0.f;
    float out[DKH];
#pragma unroll
    for (int c = 0; c < DKH; c++) out[c] = 0.f;
    const float scale = 0.17677669529663687f;  // 1/sqrt(32)
    for (int k = 0; k < LL; k++) {
        float s = 0.f;
#pragma unroll
        for (int c = 0; c < DKH; c++) s += q[c] * Ks[k][c];
        s = s * scale * wave[k];
        float mn = fmaxf(m, s);
        float c1 = __expf(m - mn);
        float p  = __expf(s - mn);
        lsum = lsum * c1 + p;
#pragma unroll
        for (int c = 0; c < DKH; c++) out[c] = out[c]*c1 + p * Vs[k][c];
        m = mn;
    }
    float inv = 1.0f / lsum;
#pragma unroll
    for (int c = 0; c < DKH; c++) g_attn[qb + c] = out[c] * inv;
}

// ---------------- MoE routing ----------------
__global__ void zero_counts_kernel() {
    if (threadIdx.x < NE) g_counts[threadIdx.x] = 0;
}

__global__ void router_kernel(const float* __restrict__ rw, const float* __restrict__ rb)
{
    int warp = (blockIdx.x * blockDim.x + threadIdx.x) >> 5;
    int lane = threadIdx.x & 31;
    if (warp >= TT) return;
    const float* hrow = g_h + (size_t)warp * DD;
    float acc[NE] = {};
    for (int d = lane; d < DD; d += 32) {
        float hv = hrow[d];
#pragma unroll
        for (int e = 0; e < NE; e++) acc[e] += hv * rw[d*NE + e];
    }
#pragma unroll
    for (int e = 0; e < NE; e++)
#pragma unroll
        for (int o = 16; o > 0; o >>= 1)
            acc[e] += __shfl_xor_sync(0xffffffff, acc[e], o);
    if (lane == 0) {
        float l[NE];
#pragma unroll
        for (int e = 0; e < NE; e++) l[e] = acc[e] + rb[e];
        int i0 = 0;
#pragma unroll
        for (int e = 1; e < NE; e++) if (l[e] > l[i0]) i0 = e;
        int i1 = -1;
#pragma unroll
        for (int e = 0; e < NE; e++) {
            if (e == i0) continue;
            if (i1 < 0 || l[e] > l[i1]) i1 = e;
        }
        // normalized top-2 softmax weights == sigmoid of logit diff
        float w0 = 1.0f / (1.0f + expf(l[i1] - l[i0]));
        g_tok_i0[warp] = i0; g_tok_i1[warp] = i1;
        g_tok_w0[warp] = w0; g_tok_w1[warp] = 1.0f - w0;
        atomicAdd(&g_counts[i0], 1);
        atomicAdd(&g_counts[i1], 1);
    }
}

__global__ void offsets_kernel() {
    int off = 0, nt = 0;
    for (int e = 0; e < NE; e++) {
        g_offs[e] = off; g_cursor[e] = off;
        int c = g_counts[e];
        int tiles = (c + TILE_M - 1) / TILE_M;
        for (int t = 0; t < tiles; t++) {
            g_tile_e[nt] = e;
            g_tile_start[nt] = off + t*TILE_M;
            g_tile_end[nt] = off + c;
            nt++;
        }
        off += c;
    }
    g_offs[NE] = off;
    g_ntiles = nt;
}

__global__ void scatter_kernel() {
    int t = blockIdx.x * blockDim.x + threadIdx.x;
    if (t >= TT) return;
    int i0 = g_tok_i0[t], i1 = g_tok_i1[t];
    int p0 = atomicAdd(&g_cursor[i0], 1);
    g_entry_token[p0] = t; g_tok_slot0[t] = p0;
    int p1 = atomicAdd(&g_cursor[i1], 1);
    g_entry_token[p1] = t; g_tok_slot1[t] = p1;
}

// deterministic combine: h[t] += w0*out2[slot0] + w1*out2[slot1]
__global__ void combine_kernel() {
    int idx = blockIdx.x * 256 + threadIdx.x;
    if (idx >= TT*DD) return;
    int t = idx / DD, n = idx % DD;
    float v = g_tok_w0[t] * g_out2[(size_t)g_tok_slot0[t]*DD + n]
            + g_tok_w1[t] * g_out2[(size_t)g_tok_slot1[t]*DD + n];
    g_h[idx] += v;
}

// ---------------- final layernorm (last token only) + heads ----------------
__global__ void head_kernel(const float* __restrict__ ln_g, const float* __restrict__ ln_b,
                            const float* __restrict__ pw, const float* __restrict__ pb,
                            const float* __restrict__ uw, const float* __restrict__ ub,
                            float* __restrict__ out)
{
    int b = blockIdx.x;
    int tid = threadIdx.x;   // 256 = D
    __shared__ float red[256];
    float v = g_h[((size_t)b*LL + (LL-1))*DD + tid];
    red[tid] = v; __syncthreads();
    for (int s = 128; s > 0; s >>= 1) { if (tid < s) red[tid] += red[tid+s]; __syncthreads(); }
    float mean = red[0] * (1.0f/DD); __syncthreads();
    float dv = v - mean;
    red[tid] = dv*dv; __syncthreads();
    for (int s = 128; s > 0; s >>= 1) { if (tid < s) red[tid] += red[tid+s]; __syncthreads(); }
    float var = red[0] * (1.0f/DD); __syncthreads();
    float hn = dv * rsqrtf(var + 1e-5f) * ln_g[tid] + ln_b[tid];

    for (int j = 0; j < NHEADS; j++) {
        red[tid] = hn * pw[tid*NHEADS + j]; __syncthreads();
        for (int s = 128; s > 0; s >>= 1) { if (tid < s) red[tid] += red[tid+s]; __syncthreads(); }
        if (tid == 0) out[b*NHEADS + j] = red[0] + pb[j];
        __syncthreads();
        red[tid] = hn * uw[tid*NHEADS + j]; __syncthreads();
        for (int s = 128; s > 0; s >>= 1) { if (tid < s) red[tid] += red[tid+s]; __syncthreads(); }
        if (tid == 0) {
            float xv = red[0] + ub[j];
            float sp = (xv > 0.f) ? (xv + log1pf(expf(-xv))) : log1pf(expf(xv));
            out[BB*NHEADS + b*NHEADS + j] = sp;
        }
        __syncthreads();
    }
}

// ---------------- host driver ----------------
static float* symaddr(const void* sym) {
    void* p = nullptr;
    cudaGetSymbolAddress(&p, sym);
    return (float*)p;
}

extern "C" void kernel_launch(void* const* d_in, const int* in_sizes, int n_in,
                              void* d_out, int out_size)
{
    const float* x        = (const float*)d_in[0];
    const float* emb_w    = (const float*)d_in[1];
    const float* emb_b    = (const float*)d_in[2];
    const float* qw       = (const float*)d_in[3];
    const float* kw       = (const float*)d_in[4];
    const float* vw       = (const float*)d_in[5];
    const float* ow       = (const float*)d_in[6];
    const float* wfreq    = (const float*)d_in[7];
    const float* wphase   = (const float*)d_in[8];
    const float* router_w = (const float*)d_in[9];
    const float* router_b = (const float*)d_in[10];
    const float* e_w1     = (const float*)d_in[11];
    const float* e_b1     = (const float*)d_in[12];
    const float* e_w2     = (const float*)d_in[13];
    const float* e_b2     = (const float*)d_in[14];
    const float* ln_g     = (const float*)d_in[15];
    const float* ln_b     = (const float*)d_in[16];
    const float* pred_w   = (const float*)d_in[17];
    const float* pred_b   = (const float*)d_in[18];
    const float* unc_w    = (const float*)d_in[19];
    const float* unc_b    = (const float*)d_in[20];
    float* out = (float*)d_out;

    float* ph    = symaddr(g_h);
    float* pq    = symaddr(g_q);
    float* pk    = symaddr(g_k);
    float* pv    = symaddr(g_v);
    float* pattn = symaddr(g_attn);
    float* pff   = symaddr(g_ff);
    float* pout2 = symaddr(g_out2);

    embed_kernel<<<(TT*DD)/256, 256>>>(x, emb_w, emb_b);

    dim3 gproj(TT/128, DD/128);   // 256 x 2
    for (int i = 0; i < NLAYER; i++) {
        const float* qwi = qw + (size_t)i*DD*DD;
        const float* kwi = kw + (size_t)i*DD*DD;
        const float* vwi = vw + (size_t)i*DD*DD;
        const float* owi = ow + (size_t)i*DD*DD;
        gemm128<0><<<gproj, 256>>>(ph, qwi, nullptr, nullptr, pq, TT, DD, DD);
        gemm128<0><<<gproj, 256>>>(ph, kwi, nullptr, nullptr, pk, TT, DD, DD);
        gemm128<0><<<gproj, 256>>>(ph, vwi, nullptr, nullptr, pv, TT, DD, DD);
        attn_kernel<<<BB*HH, 128>>>(wfreq, wphase, i);
        // h = attn_out @ ow + h   (residual fused; in-place on h is safe)
        gemm128<0><<<gproj, 256>>>(pattn, owi, nullptr, ph, ph, TT, DD, DD);

        if (i % 2 == 0 && i/2 < NMOE_L) {
            int j = i / 2;
            zero_counts_kernel<<<1, 32>>>();
            router_kernel<<<TT/8, 256>>>(router_w + (size_t)j*DD*NE, router_b + (size_t)j*NE);
            offsets_kernel<<<1, 1>>>();
            scatter_kernel<<<TT/256, 256>>>();
            gemm128<1><<<dim3(MAX_TILES, FFD/128), 256>>>(
                ph, e_w1 + (size_t)j*NE*DD*FFD, e_b1 + (size_t)j*NE*FFD,
                nullptr, pff, 0, FFD, DD);
            gemm128<2><<<dim3(MAX_TILES, DD/128), 256>>>(
                pff, e_w2 + (size_t)j*NE*FFD*DD, e_b2 + (size_t)j*NE*DD,
                nullptr, pout2, 0, DD, FFD);
            combine_kernel<<<(TT*DD)/256, 256>>>();
        }
    }

    head_kernel<<<BB, 256>>>(ln_g, ln_b, pred_w, pred_b, unc_w, unc_b, out);
}

// round 7
// speedup vs baseline: 1.9651x; 1.9651x over previous
#include <cuda_runtime.h>
#include <cuda_bf16.h>
#include <math.h>
#include <stdint.h>

#define BB 256
#define LL 128
#define IN_DIM 6
#define DD 256
#define HH 8
#define NLAYER 6
#define NE 8
#define NTOPK 2
#define FFD 1024
#define NHEADS 5
#define NMOE_L 3
#define DKH 32
#define TT (BB*LL)            // 32768 tokens
#define NENT (TT*NTOPK)       // 65536 routed entries
#define TILE_M 128
#define MAX_TILES (NENT/TILE_M + NE)   // 520

// ---------------- scratch (static device globals; no allocation) ----------------
__device__ float g_h[TT*DD];
__device__ float g_q[TT*DD];
__device__ float g_k[TT*DD];
__device__ float g_v[TT*DD];
__device__ float g_attn[TT*DD];
__device__ float g_ff[(size_t)NENT*FFD];   // 256 MB expert-hidden
__device__ float g_out2[(size_t)NENT*DD];  // 67 MB expert outputs (pre-combine)
__device__ int   g_entry_token[NENT];
__device__ int   g_tok_i0[TT], g_tok_i1[TT];
__device__ int   g_tok_slot0[TT], g_tok_slot1[TT];
__device__ float g_tok_w0[TT], g_tok_w1[TT];
__device__ int   g_counts[NE], g_offs[NE+1], g_cursor[NE];
__device__ int   g_tile_e[MAX_TILES], g_tile_start[MAX_TILES], g_tile_end[MAX_TILES];
__device__ int   g_ntiles;
// transposed (K-major, [N][K]) weights
__device__ float g_qwt[NLAYER*DD*DD];
__device__ float g_kwt[NLAYER*DD*DD];
__device__ float g_vwt[NLAYER*DD*DD];
__device__ float g_owt[NLAYER*DD*DD];
__device__ float g_w1t[(size_t)NMOE_L*NE*DD*FFD];
__device__ float g_w2t[(size_t)NMOE_L*NE*FFD*DD];

// ---------------- mma.sync helpers (baseline PTX, compiles for sm_103) ----------------
__device__ __forceinline__ uint32_t f2tf32(float f) {
    uint32_t r;
    asm("cvt.rna.tf32.f32 %0, %1;" : "=r"(r) : "f"(f));
    return r;
}
__device__ __forceinline__ void mma_tf32(float* d, const uint32_t* a, uint32_t b0, uint32_t b1) {
    asm volatile("mma.sync.aligned.m16n8k8.row.col.f32.tf32.tf32.f32 "
        "{%0,%1,%2,%3}, {%4,%5,%6,%7}, {%8,%9}, {%0,%1,%2,%3};"
        : "+f"(d[0]), "+f"(d[1]), "+f"(d[2]), "+f"(d[3])
        : "r"(a[0]), "r"(a[1]), "r"(a[2]), "r"(a[3]), "r"(b0), "r"(b1));
}

// ---------------- weight transpose: out[n*K+k] = in[k*N+n], batched over z ----------------
__global__ void transpose_kernel(const float* __restrict__ in, float* __restrict__ out,
                                 int K, int N) {
    __shared__ float t[32][33];
    size_t mo = (size_t)blockIdx.z * K * N;
    const float* ip = in + mo;
    float* op = out + mo;
    int k0 = blockIdx.x * 32, n0 = blockIdx.y * 32;
    int tx = threadIdx.x, ty = threadIdx.y;
    for (int i = ty; i < 32; i += 8) t[i][tx] = ip[(size_t)(k0 + i) * N + n0 + tx];
    __syncthreads();
    for (int i = ty; i < 32; i += 8) op[(size_t)(n0 + i) * K + k0 + tx] = t[tx][i];
}

// ---------------- embedding ----------------
__global__ void embed_kernel(const float* __restrict__ x,
                             const float* __restrict__ ew,
                             const float* __restrict__ eb) {
    int idx = blockIdx.x * 256 + threadIdx.x;
    if (idx >= TT*DD) return;
    int t = idx / DD, d = idx % DD;
    const float* xr = x + t * IN_DIM;
    float s = eb[d];
#pragma unroll
    for (int c = 0; c < IN_DIM; c++) s += xr[c] * ew[c*DD + d];
    g_h[idx] = s;
}

// ---------------- tf32 mma.sync GEMM: 128x128 tile, 8 warps, K chunks of 32 ----------------
// A: [rows][K] fp32 (rows selected per MODE). Bt: [N][K] fp32 K-major (pre-transposed W).
// MODE 0: C = A@W (+Res);  MODE 1: MoE up (gather + gelu + b1);  MODE 2: MoE down (+b2)
#define SAST 36   // smem row stride (floats): conflict-free + 16B aligned
template<int MODE>
__global__ void __launch_bounds__(256) tgemm(
    const float* __restrict__ A, const float* __restrict__ Bt,
    const float* __restrict__ bias, const float* __restrict__ Res,
    float* __restrict__ C, int K, int Nfull)
{
    __shared__ uint32_t As[128*SAST];
    __shared__ uint32_t Bs[128*SAST];
    __shared__ const float* aptr[128];

    int tile = blockIdx.x;
    int n0 = blockIdx.y * 128;
    int m0 = 0, row_start = 0, row_end = 0;
    const float* Bte = Bt;
    const float* biasp = bias;
    if (MODE == 0) {
        m0 = tile * 128;
    } else {
        if (tile >= g_ntiles) return;
        int e = g_tile_e[tile];
        row_start = g_tile_start[tile];
        row_end   = g_tile_end[tile];
        Bte   = Bt + (size_t)e * K * Nfull;
        biasp = bias + (size_t)e * Nfull;
    }
    int tid = threadIdx.x;
    int warp = tid >> 5, lane = tid & 31;
    int wm = warp & 3, wn = warp >> 2;        // 4 m-warps x 2 n-warps
    int gid = lane >> 2, tq = lane & 3;

    if (tid < 128) {
        const float* p;
        if (MODE == 0) {
            p = A + (size_t)(m0 + tid) * K;
        } else if (MODE == 1) {
            int slot = row_start + tid;
            int tok = (slot < row_end) ? g_entry_token[slot] : 0;
            if (tok < 0 || tok >= TT) tok = 0;
            p = A + (size_t)tok * K;
        } else {
            int slot = row_start + tid;
            if (slot >= NENT) slot = NENT - 1;
            p = A + (size_t)slot * K;
        }
        aptr[tid] = p;
    }
    __syncthreads();

    // fill mapping: 1024 float4 per matrix per chunk, 4 per thread
    int rowF[4], qF[4];
#pragma unroll
    for (int i = 0; i < 4; i++) {
        int fid = tid + i*256;
        rowF[i] = fid >> 3;
        qF[i]   = fid & 7;
    }
    float4 pa[4], pb[4];
#pragma unroll
    for (int i = 0; i < 4; i++) {
        pa[i] = *reinterpret_cast<const float4*>(aptr[rowF[i]] + qF[i]*4);
        pb[i] = *reinterpret_cast<const float4*>(Bte + (size_t)(n0 + rowF[i]) * K + qF[i]*4);
    }

    float acc[2][8][4];
#pragma unroll
    for (int mi = 0; mi < 2; mi++)
#pragma unroll
        for (int nf = 0; nf < 8; nf++)
#pragma unroll
            for (int c = 0; c < 4; c++) acc[mi][nf][c] = 0.f;

    for (int kc = 0; kc < K; kc += 32) {
        // store current chunk to smem (tf32-rounded)
#pragma unroll
        for (int i = 0; i < 4; i++) {
            uint32_t* d = &As[rowF[i]*SAST + qF[i]*4];
            d[0] = f2tf32(pa[i].x); d[1] = f2tf32(pa[i].y);
            d[2] = f2tf32(pa[i].z); d[3] = f2tf32(pa[i].w);
            uint32_t* e = &Bs[rowF[i]*SAST + qF[i]*4];
            e[0] = f2tf32(pb[i].x); e[1] = f2tf32(pb[i].y);
            e[2] = f2tf32(pb[i].z); e[3] = f2tf32(pb[i].w);
        }
        __syncthreads();
        // prefetch next chunk (overlaps mma block)
        if (kc + 32 < K) {
#pragma unroll
            for (int i = 0; i < 4; i++) {
                pa[i] = *reinterpret_cast<const float4*>(aptr[rowF[i]] + kc + 32 + qF[i]*4);
                pb[i] = *reinterpret_cast<const float4*>(Bte + (size_t)(n0 + rowF[i]) * K + kc + 32 + qF[i]*4);
            }
        }
#pragma unroll
        for (int ks = 0; ks < 32; ks += 8) {
            uint32_t af[2][4];
#pragma unroll
            for (int mi = 0; mi < 2; mi++) {
                int r = wm*32 + mi*16 + gid;
                af[mi][0] = As[r*SAST + ks + tq];
                af[mi][1] = As[(r+8)*SAST + ks + tq];
                af[mi][2] = As[r*SAST + ks + tq + 4];
                af[mi][3] = As[(r+8)*SAST + ks + tq + 4];
            }
#pragma unroll
            for (int nf = 0; nf < 8; nf++) {
                int nn = wn*64 + nf*8 + gid;
                uint32_t b0 = Bs[nn*SAST + ks + tq];
                uint32_t b1 = Bs[nn*SAST + ks + tq + 4];
                mma_tf32(acc[0][nf], af[0], b0, b1);
                mma_tf32(acc[1][nf], af[1], b0, b1);
            }
        }
        __syncthreads();
    }

    // epilogue: c0/c1 at (gid, 2tq), c2/c3 at (gid+8, 2tq)
#pragma unroll
    for (int mi = 0; mi < 2; mi++) {
#pragma unroll
        for (int half = 0; half < 2; half++) {
            int r = wm*32 + mi*16 + gid + half*8;
#pragma unroll
            for (int nf = 0; nf < 8; nf++) {
                float v0 = acc[mi][nf][half*2 + 0];
                float v1 = acc[mi][nf][half*2 + 1];
                int n = n0 + wn*64 + nf*8 + tq*2;
                if (MODE == 0) {
                    int m = m0 + r;
                    size_t o = (size_t)m*Nfull + n;
                    if (Res) { v0 += Res[o]; v1 += Res[o+1]; }
                    *reinterpret_cast<float2*>(&C[o]) = make_float2(v0, v1);
                } else if (MODE == 1) {
                    int slot = row_start + r;
                    if (slot < row_end) {
                        float x0 = v0 + biasp[n], x1 = v1 + biasp[n+1];
                        float g0 = 0.5f*x0*(1.0f + erff(x0*0.7071067811865475f));
                        float g1 = 0.5f*x1*(1.0f + erff(x1*0.7071067811865475f));
                        *reinterpret_cast<float2*>(&C[(size_t)slot*Nfull + n]) = make_float2(g0, g1);
                    }
                } else {
                    int slot = row_start + r;
                    if (slot < row_end) {
                        *reinterpret_cast<float2*>(&C[(size_t)slot*Nfull + n]) =
                            make_float2(v0 + biasp[n], v1 + biasp[n+1]);
                    }
                }
            }
        }
    }
}

// ---------------- fused wave attention: one block per (b,h) ----------------
__global__ void attn_kernel(const float* __restrict__ wfreq,
                            const float* __restrict__ wphase, int layer)
{
    __shared__ float Ks[LL][DKH];
    __shared__ float Vs[LL][DKH];
    __shared__ float wave[LL];
    int bh = blockIdx.x;
    int b = bh / HH, h = bh % HH;
    int tid = threadIdx.x;                // 128 threads: 1 query row each
    float fr = wfreq[layer*HH + h];
    float ph = wphase[layer*HH + h];
    size_t base = ((size_t)b * LL) * DD + h * DKH;
    for (int idx = tid; idx < LL*DKH; idx += 128) {
        int r = idx >> 5, c = idx & 31;
        Ks[r][c] = g_k[base + (size_t)r*DD + c];
        Vs[r][c] = g_v[base + (size_t)r*DD + c];
    }
    if (tid < LL) wave[tid] = cosf(6.283185307179586f * fr * (float)tid + ph);
    __syncthreads();

    float q[DKH];
    size_t qb = base + (size_t)tid * DD;
#pragma unroll
    for (int c = 0; c < DKH; c++) q[c] = g_q[qb + c];

    float m = -1e30f, lsum = 0.f;
    float out[DKH];
#pragma unroll
    for (int c = 0; c < DKH; c++) out[c] = 0.f;
    const float scale = 0.17677669529663687f;  // 1/sqrt(32)
    for (int k = 0; k < LL; k++) {
        float s = 0.f;
#pragma unroll
        for (int c = 0; c < DKH; c++) s += q[c] * Ks[k][c];
        s = s * scale * wave[k];
        float mn = fmaxf(m, s);
        float c1 = __expf(m - mn);
        float p  = __expf(s - mn);
        lsum = lsum * c1 + p;
#pragma unroll
        for (int c = 0; c < DKH; c++) out[c] = out[c]*c1 + p * Vs[k][c];
        m = mn;
    }
    float inv = 1.0f / lsum;
#pragma unroll
    for (int c = 0; c < DKH; c++) g_attn[qb + c] = out[c] * inv;
}

// ---------------- MoE routing ----------------
__global__ void zero_counts_kernel() {
    if (threadIdx.x < NE) g_counts[threadIdx.x] = 0;
}

__global__ void router_kernel(const float* __restrict__ rw, const float* __restrict__ rb)
{
    int warp = (blockIdx.x * blockDim.x + threadIdx.x) >> 5;
    int lane = threadIdx.x & 31;
    if (warp >= TT) return;
    const float* hrow = g_h + (size_t)warp * DD;
    float acc[NE] = {};
    for (int d = lane; d < DD; d += 32) {
        float hv = hrow[d];
#pragma unroll
        for (int e = 0; e < NE; e++) acc[e] += hv * rw[d*NE + e];
    }
#pragma unroll
    for (int e = 0; e < NE; e++)
#pragma unroll
        for (int o = 16; o > 0; o >>= 1)
            acc[e] += __shfl_xor_sync(0xffffffff, acc[e], o);
    if (lane == 0) {
        float l[NE];
#pragma unroll
        for (int e = 0; e < NE; e++) l[e] = acc[e] + rb[e];
        int i0 = 0;
#pragma unroll
        for (int e = 1; e < NE; e++) if (l[e] > l[i0]) i0 = e;
        int i1 = -1;
#pragma unroll
        for (int e = 0; e < NE; e++) {
            if (e == i0) continue;
            if (i1 < 0 || l[e] > l[i1]) i1 = e;
        }
        float w0 = 1.0f / (1.0f + expf(l[i1] - l[i0]));
        g_tok_i0[warp] = i0; g_tok_i1[warp] = i1;
        g_tok_w0[warp] = w0; g_tok_w1[warp] = 1.0f - w0;
        atomicAdd(&g_counts[i0], 1);
        atomicAdd(&g_counts[i1], 1);
    }
}

__global__ void offsets_kernel() {
    int off = 0, nt = 0;
    for (int e = 0; e < NE; e++) {
        g_offs[e] = off; g_cursor[e] = off;
        int c = g_counts[e];
        int tiles = (c + TILE_M - 1) / TILE_M;
        for (int t = 0; t < tiles; t++) {
            g_tile_e[nt] = e;
            g_tile_start[nt] = off + t*TILE_M;
            g_tile_end[nt] = off + c;
            nt++;
        }
        off += c;
    }
    g_offs[NE] = off;
    g_ntiles = nt;
}

__global__ void scatter_kernel() {
    int t = blockIdx.x * blockDim.x + threadIdx.x;
    if (t >= TT) return;
    int i0 = g_tok_i0[t], i1 = g_tok_i1[t];
    int p0 = atomicAdd(&g_cursor[i0], 1);
    g_entry_token[p0] = t; g_tok_slot0[t] = p0;
    int p1 = atomicAdd(&g_cursor[i1], 1);
    g_entry_token[p1] = t; g_tok_slot1[t] = p1;
}

// deterministic combine: h[t] += w0*out2[slot0] + w1*out2[slot1]
__global__ void combine_kernel() {
    int idx = blockIdx.x * 256 + threadIdx.x;
    if (idx >= TT*DD) return;
    int t = idx / DD, n = idx % DD;
    float v = g_tok_w0[t] * g_out2[(size_t)g_tok_slot0[t]*DD + n]
            + g_tok_w1[t] * g_out2[(size_t)g_tok_slot1[t]*DD + n];
    g_h[idx] += v;
}

// ---------------- final layernorm (last token only) + heads ----------------
__global__ void head_kernel(const float* __restrict__ ln_g, const float* __restrict__ ln_b,
                            const float* __restrict__ pw, const float* __restrict__ pb,
                            const float* __restrict__ uw, const float* __restrict__ ub,
                            float* __restrict__ out)
{
    int b = blockIdx.x;
    int tid = threadIdx.x;   // 256 = D
    __shared__ float red[256];
    float v = g_h[((size_t)b*LL + (LL-1))*DD + tid];
    red[tid] = v; __syncthreads();
    for (int s = 128; s > 0; s >>= 1) { if (tid < s) red[tid] += red[tid+s]; __syncthreads(); }
    float mean = red[0] * (1.0f/DD); __syncthreads();
    float dv = v - mean;
    red[tid] = dv*dv; __syncthreads();
    for (int s = 128; s > 0; s >>= 1) { if (tid < s) red[tid] += red[tid+s]; __syncthreads(); }
    float var = red[0] * (1.0f/DD); __syncthreads();
    float hn = dv * rsqrtf(var + 1e-5f) * ln_g[tid] + ln_b[tid];

    for (int j = 0; j < NHEADS; j++) {
        red[tid] = hn * pw[tid*NHEADS + j]; __syncthreads();
        for (int s = 128; s > 0; s >>= 1) { if (tid < s) red[tid] += red[tid+s]; __syncthreads(); }
        if (tid == 0) out[b*NHEADS + j] = red[0] + pb[j];
        __syncthreads();
        red[tid] = hn * uw[tid*NHEADS + j]; __syncthreads();
        for (int s = 128; s > 0; s >>= 1) { if (tid < s) red[tid] += red[tid+s]; __syncthreads(); }
        if (tid == 0) {
            float xv = red[0] + ub[j];
            float sp = (xv > 0.f) ? (xv + log1pf(expf(-xv))) : log1pf(expf(xv));
            out[BB*NHEADS + b*NHEADS + j] = sp;
        }
        __syncthreads();
    }
}

// ---------------- host driver ----------------
static float* symaddr(const void* sym) {
    void* p = nullptr;
    cudaGetSymbolAddress(&p, sym);
    return (float*)p;
}

extern "C" void kernel_launch(void* const* d_in, const int* in_sizes, int n_in,
                              void* d_out, int out_size)
{
    const float* x        = (const float*)d_in[0];
    const float* emb_w    = (const float*)d_in[1];
    const float* emb_b    = (const float*)d_in[2];
    const float* qw       = (const float*)d_in[3];
    const float* kw       = (const float*)d_in[4];
    const float* vw       = (const float*)d_in[5];
    const float* ow       = (const float*)d_in[6];
    const float* wfreq    = (const float*)d_in[7];
    const float* wphase   = (const float*)d_in[8];
    const float* router_w = (const float*)d_in[9];
    const float* router_b = (const float*)d_in[10];
    const float* e_w1     = (const float*)d_in[11];
    const float* e_b1     = (const float*)d_in[12];
    const float* e_w2     = (const float*)d_in[13];
    const float* e_b2     = (const float*)d_in[14];
    const float* ln_g     = (const float*)d_in[15];
    const float* ln_b     = (const float*)d_in[16];
    const float* pred_w   = (const float*)d_in[17];
    const float* pred_b   = (const float*)d_in[18];
    const float* unc_w    = (const float*)d_in[19];
    const float* unc_b    = (const float*)d_in[20];
    float* out = (float*)d_out;

    float* ph    = symaddr(g_h);
    float* pq    = symaddr(g_q);
    float* pk    = symaddr(g_k);
    float* pv    = symaddr(g_v);
    float* pattn = symaddr(g_attn);
    float* pff   = symaddr(g_ff);
    float* pout2 = symaddr(g_out2);
    float* pqwt  = symaddr(g_qwt);
    float* pkwt  = symaddr(g_kwt);
    float* pvwt  = symaddr(g_vwt);
    float* powt  = symaddr(g_owt);
    float* pw1t  = symaddr(g_w1t);
    float* pw2t  = symaddr(g_w2t);

    // transpose all weights to K-major [N][K]
    dim3 tb(32, 8);
    transpose_kernel<<<dim3(DD/32, DD/32, NLAYER), tb>>>(qw, pqwt, DD, DD);
    transpose_kernel<<<dim3(DD/32, DD/32, NLAYER), tb>>>(kw, pkwt, DD, DD);
    transpose_kernel<<<dim3(DD/32, DD/32, NLAYER), tb>>>(vw, pvwt, DD, DD);
    transpose_kernel<<<dim3(DD/32, DD/32, NLAYER), tb>>>(ow, powt, DD, DD);
    transpose_kernel<<<dim3(DD/32, FFD/32, NMOE_L*NE), tb>>>(e_w1, pw1t, DD, FFD);
    transpose_kernel<<<dim3(FFD/32, DD/32, NMOE_L*NE), tb>>>(e_w2, pw2t, FFD, DD);

    embed_kernel<<<(TT*DD)/256, 256>>>(x, emb_w, emb_b);

    dim3 gproj(TT/128, DD/128);   // 256 x 2
    for (int i = 0; i < NLAYER; i++) {
        tgemm<0><<<gproj, 256>>>(ph, pqwt + (size_t)i*DD*DD, nullptr, nullptr, pq, DD, DD);
        tgemm<0><<<gproj, 256>>>(ph, pkwt + (size_t)i*DD*DD, nullptr, nullptr, pk, DD, DD);
        tgemm<0><<<gproj, 256>>>(ph, pvwt + (size_t)i*DD*DD, nullptr, nullptr, pv, DD, DD);
        attn_kernel<<<BB*HH, 128>>>(wfreq, wphase, i);
        // h = attn_out @ ow + h (residual fused)
        tgemm<0><<<gproj, 256>>>(pattn, powt + (size_t)i*DD*DD, nullptr, ph, ph, DD, DD);

        if (i % 2 == 0 && i/2 < NMOE_L) {
            int j = i / 2;
            zero_counts_kernel<<<1, 32>>>();
            router_kernel<<<TT/8, 256>>>(router_w + (size_t)j*DD*NE, router_b + (size_t)j*NE);
            offsets_kernel<<<1, 1>>>();
            scatter_kernel<<<TT/256, 256>>>();
            tgemm<1><<<dim3(MAX_TILES, FFD/128), 256>>>(
                ph, pw1t + (size_t)j*NE*DD*FFD, e_b1 + (size_t)j*NE*FFD,
                nullptr, pff, DD, FFD);
            tgemm<2><<<dim3(MAX_TILES, DD/128), 256>>>(
                pff, pw2t + (size_t)j*NE*FFD*DD, e_b2 + (size_t)j*NE*DD,
                nullptr, pout2, FFD, DD);
            combine_kernel<<<(TT*DD)/256, 256>>>();
        }
    }

    head_kernel<<<BB, 256>>>(ln_g, ln_b, pred_w, pred_b, unc_w, unc_b, out);
}